// round 1
// baseline (speedup 1.0000x reference)
#include <cuda_runtime.h>
#include <cstdint>
#include <cstddef>

// ---------------- scratch (no allocations allowed) ----------------
__device__ float g_WihT[1034 * 1536];      // W_ih transposed: [k][col]
__device__ float g_gx[2048 * 1536];
__device__ float g_gh[2048 * 1536];
__device__ float g_h1[2048 * 512];
__device__ float g_logits[2048 * 1024];
__device__ int   g_idx[2048 * 32];

// ---------------- threefry2x32 (20 rounds) ----------------
__host__ __device__ __forceinline__ void tf_round(unsigned &x0, unsigned &x1, int r) {
    x0 += x1;
    x1 = (x1 << r) | (x1 >> (32 - r));
    x1 ^= x0;
}
__host__ __device__ __forceinline__ void threefry2x32(unsigned k0, unsigned k1,
                                                      unsigned &x0, unsigned &x1) {
    unsigned k2 = k0 ^ k1 ^ 0x1BD11BDAu;
    x0 += k0; x1 += k1;
    tf_round(x0, x1, 13); tf_round(x0, x1, 15); tf_round(x0, x1, 26); tf_round(x0, x1, 6);
    x0 += k1; x1 += k2 + 1u;
    tf_round(x0, x1, 17); tf_round(x0, x1, 29); tf_round(x0, x1, 16); tf_round(x0, x1, 24);
    x0 += k2; x1 += k0 + 2u;
    tf_round(x0, x1, 13); tf_round(x0, x1, 15); tf_round(x0, x1, 26); tf_round(x0, x1, 6);
    x0 += k0; x1 += k1 + 3u;
    tf_round(x0, x1, 17); tf_round(x0, x1, 29); tf_round(x0, x1, 16); tf_round(x0, x1, 24);
    x0 += k1; x1 += k2 + 4u;
    tf_round(x0, x1, 13); tf_round(x0, x1, 15); tf_round(x0, x1, 26); tf_round(x0, x1, 6);
    x0 += k2; x1 += k0 + 5u;
}

// sigmoid matching XLA's logistic lowering: 0.5 + 0.5*tanh(0.5 x)
__device__ __forceinline__ float sigmoid_x(float x) {
    return 0.5f * tanhf(0.5f * x) + 0.5f;
}

// ---------------- transpose W_ih [1536][1034] -> WT [1034][1536] ----------------
__global__ void transpose_k(const float* __restrict__ W, float* __restrict__ WT,
                            int R, int Cc) {
    __shared__ float tile[32][33];
    int c0 = blockIdx.x * 32, r0 = blockIdx.y * 32;
    int c = c0 + threadIdx.x, r = r0 + threadIdx.y;
    if (r < R && c < Cc) tile[threadIdx.y][threadIdx.x] = W[(size_t)r * Cc + c];
    __syncthreads();
    int tc = c0 + threadIdx.y, tr = r0 + threadIdx.x;
    if (tc < Cc && tr < R) WT[(size_t)tc * R + tr] = tile[threadIdx.x][threadIdx.y];
}

// ---------------- gx gather: one block per batch row, 384 thr (4 cols each) ----------------
__global__ void __launch_bounds__(384) gather_gx(
    const float* __restrict__ WT,      // [1034][1536]
    const float* __restrict__ b_ih,    // [1536]
    const int*   __restrict__ idx,     // [2048][32]
    const float* __restrict__ act,     // [2048][10]
    float* __restrict__ gx, int use_stoch)
{
    int b = blockIdx.x;
    __shared__ int   sidx[32];
    __shared__ float sact[10];
    int t = threadIdx.x;
    if (t < 32 && use_stoch) sidx[t] = idx[b * 32 + t];
    if (t < 10) sact[t] = act[b * 10 + t];
    __syncthreads();
    int j = t * 4;
    float4 acc = *(const float4*)(b_ih + j);
    if (use_stoch) {
        #pragma unroll 4
        for (int s = 0; s < 32; s++) {
            const float4 w = *(const float4*)(WT + (size_t)(s * 32 + sidx[s]) * 1536 + j);
            acc.x += w.x; acc.y += w.y; acc.z += w.z; acc.w += w.w;
        }
    }
    #pragma unroll
    for (int a = 0; a < 10; a++) {
        float av = sact[a];
        const float4 w = *(const float4*)(WT + (size_t)(1024 + a) * 1536 + j);
        acc.x = fmaf(av, w.x, acc.x); acc.y = fmaf(av, w.y, acc.y);
        acc.z = fmaf(av, w.z, acc.z); acc.w = fmaf(av, w.w, acc.w);
    }
    *(float4*)(gx + (size_t)b * 1536 + j) = acc;
}

// ---------------- SGEMM: C[m][n] = sum_k A[m][k]*B[n][k]; 128x128 tile, BK=8 ----------------
__global__ void __launch_bounds__(256) sgemm_nt(
    const float* __restrict__ A, int lda,
    const float* __restrict__ B, int ldb,
    float* __restrict__ C, int ldc, int K)
{
    __shared__ float As[8][128];
    __shared__ float Bs[8][128];
    const int bm = blockIdx.y * 128;
    const int bn = blockIdx.x * 128;
    const int tid = threadIdx.x;
    const int lr = tid >> 1;
    const int lc = (tid & 1) << 2;
    const float* Ap = A + (size_t)(bm + lr) * lda + lc;
    const float* Bp = B + (size_t)(bn + lr) * ldb + lc;
    const int tx = tid & 15;
    const int ty = tid >> 4;
    const int mr = ty << 3;
    const int nc = tx << 3;
    float acc[8][8];
    #pragma unroll
    for (int i = 0; i < 8; i++)
        #pragma unroll
        for (int j = 0; j < 8; j++) acc[i][j] = 0.f;

    for (int k0 = 0; k0 < K; k0 += 8) {
        float4 av = *(const float4*)(Ap + k0);
        float4 bv = *(const float4*)(Bp + k0);
        As[lc + 0][lr] = av.x; As[lc + 1][lr] = av.y;
        As[lc + 2][lr] = av.z; As[lc + 3][lr] = av.w;
        Bs[lc + 0][lr] = bv.x; Bs[lc + 1][lr] = bv.y;
        Bs[lc + 2][lr] = bv.z; Bs[lc + 3][lr] = bv.w;
        __syncthreads();
        #pragma unroll
        for (int k = 0; k < 8; k++) {
            float a0[8], b0[8];
            *(float4*)(a0)     = *(const float4*)&As[k][mr];
            *(float4*)(a0 + 4) = *(const float4*)&As[k][mr + 4];
            *(float4*)(b0)     = *(const float4*)&Bs[k][nc];
            *(float4*)(b0 + 4) = *(const float4*)&Bs[k][nc + 4];
            #pragma unroll
            for (int i = 0; i < 8; i++)
                #pragma unroll
                for (int j = 0; j < 8; j++)
                    acc[i][j] = fmaf(a0[i], b0[j], acc[i][j]);
        }
        __syncthreads();
    }
    #pragma unroll
    for (int i = 0; i < 8; i++) {
        float* Crow = C + (size_t)(bm + mr + i) * ldc + bn + nc;
        *(float4*)Crow       = make_float4(acc[i][0], acc[i][1], acc[i][2], acc[i][3]);
        *(float4*)(Crow + 4) = make_float4(acc[i][4], acc[i][5], acc[i][6], acc[i][7]);
    }
}

// ---------------- GRU gate fusion: deter -> out[t][b][0:512] ----------------
__global__ void __launch_bounds__(256) gru_gates(
    const float* __restrict__ gx, const float* __restrict__ gh,
    const float* __restrict__ b_hh,
    const float* __restrict__ hprev, int ldh,
    float* __restrict__ out_t)
{
    int i = blockIdx.x * 256 + threadIdx.x;   // 2048*512 threads
    int b = i >> 9, j = i & 511;
    size_t base = (size_t)b * 1536;
    float xr = gx[base + j];
    float xz = gx[base + 512 + j];
    float xn = gx[base + 1024 + j];
    float hr = gh[base + j]        + b_hh[j];
    float hz = gh[base + 512 + j]  + b_hh[512 + j];
    float hn = gh[base + 1024 + j] + b_hh[1024 + j];
    float r = sigmoid_x(xr + hr);
    float z = sigmoid_x(xz + hz);
    float n = tanhf(xn + r * hn);
    float h = hprev[(size_t)b * ldh + j];
    out_t[base + j] = (1.f - z) * n + z * h;
}

// ---------------- LayerNorm + SiLU (warp per row of 512), in-place ok ----------------
__global__ void __launch_bounds__(256) ln_silu(
    float* __restrict__ h1, const float* __restrict__ pb1,
    const float* __restrict__ pg, const float* __restrict__ pbeta)
{
    int gw = (blockIdx.x * 256 + threadIdx.x) >> 5;   // row 0..2047
    int lane = threadIdx.x & 31;
    float* row = h1 + (size_t)gw * 512;
    float x[16];
    float s = 0.f;
    #pragma unroll
    for (int i = 0; i < 16; i++) { x[i] = row[i * 32 + lane] + pb1[i * 32 + lane]; s += x[i]; }
    #pragma unroll
    for (int o = 16; o; o >>= 1) s += __shfl_xor_sync(0xffffffffu, s, o);
    float mu = s * (1.f / 512.f);
    float vs = 0.f;
    #pragma unroll
    for (int i = 0; i < 16; i++) { float d = x[i] - mu; vs = fmaf(d, d, vs); }
    #pragma unroll
    for (int o = 16; o; o >>= 1) vs += __shfl_xor_sync(0xffffffffu, vs, o);
    float var = vs * (1.f / 512.f) + 1e-5f;
    float rs = rsqrtf(var);
    rs = rs * (1.5f - 0.5f * var * rs * rs);   // Newton refine -> ~exact
    #pragma unroll
    for (int i = 0; i < 16; i++) {
        int c = i * 32 + lane;
        float v = (x[i] - mu) * rs * pg[c] + pbeta[c];
        row[c] = v * sigmoid_x(v);             // silu
    }
}

// ---------------- categorical sampling (partitionable threefry) ----------------
__global__ void __launch_bounds__(256) sample_k(
    const float* __restrict__ logits, const float* __restrict__ pb2,
    unsigned k0, unsigned k1,
    float* __restrict__ out_t, int* __restrict__ idxbuf)
{
    int w = (blockIdx.x * 256 + threadIdx.x) >> 5;  // (b,s) pair: 65536 warps
    int lane = threadIdx.x & 31;
    int b = w >> 5, s = w & 31;
    unsigned x0 = 0u, x1 = (unsigned)(b * 1024 + s * 32 + lane);
    unsigned flat = x1;
    threefry2x32(k0, k1, x0, x1);
    unsigned bits = x0 ^ x1;
    float f = __uint_as_float((bits >> 9) | 0x3f800000u) - 1.0f;
    float u = (f == 0.f) ? 1.17549435e-38f : f;
    float g = -logf(-logf(u));
    float v = logits[(size_t)b * 1024 + s * 32 + lane] + pb2[s * 32 + lane] + g;
    float bv = v; int bi = lane;
    #pragma unroll
    for (int o = 16; o; o >>= 1) {
        float ov = __shfl_xor_sync(0xffffffffu, bv, o);
        int   oi = __shfl_xor_sync(0xffffffffu, bi, o);
        if (ov > bv || (ov == bv && oi < bi)) { bv = ov; bi = oi; }
    }
    out_t[(size_t)b * 1536 + 512 + s * 32 + lane] = (lane == bi) ? 1.0f : 0.0f;
    if (lane == bi) idxbuf[b * 32 + s] = bi;
    (void)flat;
}

// ---------------- host ----------------
extern "C" void kernel_launch(void* const* d_in, const int* in_sizes, int n_in,
                              void* d_out, int out_size) {
    const float* action = (const float*)d_in[0];
    const float* deter0 = (const float*)d_in[1];
    // d_in[2] = stoch0 (zeros by construction; step 0 skips the stoch gather)
    const float* W_ih  = (const float*)d_in[3];
    const float* b_ih  = (const float*)d_in[4];
    const float* W_hh  = (const float*)d_in[5];
    const float* b_hh  = (const float*)d_in[6];
    const float* pW1   = (const float*)d_in[7];
    const float* pb1   = (const float*)d_in[8];
    const float* pg    = (const float*)d_in[9];
    const float* pbeta = (const float*)d_in[10];
    const float* pW2   = (const float*)d_in[11];
    const float* pb2   = (const float*)d_in[12];
    float* out = (float*)d_out;

    float *WT, *gx, *gh, *h1, *logits; int* idxb;
    cudaGetSymbolAddress((void**)&WT, g_WihT);
    cudaGetSymbolAddress((void**)&gx, g_gx);
    cudaGetSymbolAddress((void**)&gh, g_gh);
    cudaGetSymbolAddress((void**)&h1, g_h1);
    cudaGetSymbolAddress((void**)&logits, g_logits);
    cudaGetSymbolAddress((void**)&idxb, g_idx);

    // step keys: split(key(42), 16) in partitionable (fold-like) mode:
    // key_t = threefry2x32((0,42), (0, t))
    unsigned kt0[16], kt1[16];
    for (int t = 0; t < 16; t++) {
        unsigned x0 = 0u, x1 = (unsigned)t;
        threefry2x32(0u, 42u, x0, x1);
        kt0[t] = x0; kt1[t] = x1;
    }

    transpose_k<<<dim3(33, 48), dim3(32, 32)>>>(W_ih, WT, 1536, 1034);

    for (int t = 0; t < 16; t++) {
        const float* act_t = action + (size_t)t * 2048 * 10;
        float* out_t = out + (size_t)t * 2048 * 1536;
        const float* hprev = t ? out + (size_t)(t - 1) * 2048 * 1536 : deter0;
        int ldh = t ? 1536 : 512;

        gather_gx<<<2048, 384>>>(WT, b_ih, idxb, act_t, gx, t > 0);
        sgemm_nt<<<dim3(12, 16), 256>>>(hprev, ldh, W_hh, 512, gh, 1536, 512);
        gru_gates<<<4096, 256>>>(gx, gh, b_hh, hprev, ldh, out_t);
        sgemm_nt<<<dim3(4, 16), 256>>>(out_t, 1536, pW1, 512, h1, 512, 512);
        ln_silu<<<256, 256>>>(h1, pb1, pg, pbeta);
        sgemm_nt<<<dim3(8, 16), 256>>>(h1, 512, pW2, 512, logits, 1024, 512);
        sample_k<<<8192, 256>>>(logits, pb2, kt0[t], kt1[t], out_t, idxb);
    }
}

// round 6
// speedup vs baseline: 1.2350x; 1.2350x over previous
#include <cuda_runtime.h>
#include <cstdint>
#include <cstddef>

// ---------------- scratch (no allocations allowed) ----------------
__device__ float g_WihT[1034 * 1536];      // W_ih transposed: [k][col]
__device__ float g_gx[2048 * 1536];
__device__ float g_gh[2048 * 1536];
__device__ float g_h1[2048 * 512];
__device__ float g_logits[2048 * 1024];
__device__ int   g_idx[2048 * 32];

// ---------------- threefry2x32 (20 rounds) ----------------
__host__ __device__ __forceinline__ void tf_round(unsigned &x0, unsigned &x1, int r) {
    x0 += x1;
    x1 = (x1 << r) | (x1 >> (32 - r));
    x1 ^= x0;
}
__host__ __device__ __forceinline__ void threefry2x32(unsigned k0, unsigned k1,
                                                      unsigned &x0, unsigned &x1) {
    unsigned k2 = k0 ^ k1 ^ 0x1BD11BDAu;
    x0 += k0; x1 += k1;
    tf_round(x0, x1, 13); tf_round(x0, x1, 15); tf_round(x0, x1, 26); tf_round(x0, x1, 6);
    x0 += k1; x1 += k2 + 1u;
    tf_round(x0, x1, 17); tf_round(x0, x1, 29); tf_round(x0, x1, 16); tf_round(x0, x1, 24);
    x0 += k2; x1 += k0 + 2u;
    tf_round(x0, x1, 13); tf_round(x0, x1, 15); tf_round(x0, x1, 26); tf_round(x0, x1, 6);
    x0 += k0; x1 += k1 + 3u;
    tf_round(x0, x1, 17); tf_round(x0, x1, 29); tf_round(x0, x1, 16); tf_round(x0, x1, 24);
    x0 += k1; x1 += k2 + 4u;
    tf_round(x0, x1, 13); tf_round(x0, x1, 15); tf_round(x0, x1, 26); tf_round(x0, x1, 6);
    x0 += k2; x1 += k0 + 5u;
}

__device__ __forceinline__ float sigmoid_x(float x) {
    return 0.5f * tanhf(0.5f * x) + 0.5f;
}

// ---------------- transpose W_ih [1536][1034] -> WT [1034][1536] ----------------
__global__ void transpose_k(const float* __restrict__ W, float* __restrict__ WT,
                            int R, int Cc) {
    __shared__ float tile[32][33];
    int c0 = blockIdx.x * 32, r0 = blockIdx.y * 32;
    int c = c0 + threadIdx.x, r = r0 + threadIdx.y;
    if (r < R && c < Cc) tile[threadIdx.y][threadIdx.x] = W[(size_t)r * Cc + c];
    __syncthreads();
    int tc = c0 + threadIdx.y, tr = r0 + threadIdx.x;
    if (tc < Cc && tr < R) WT[(size_t)tc * R + tr] = tile[threadIdx.x][threadIdx.y];
}

// ---------------- gx gather ----------------
__global__ void __launch_bounds__(384) gather_gx(
    const float* __restrict__ WT, const float* __restrict__ b_ih,
    const int* __restrict__ idx, const float* __restrict__ act,
    float* __restrict__ gx, int use_stoch)
{
    int b = blockIdx.x;
    __shared__ int   sidx[32];
    __shared__ float sact[10];
    int t = threadIdx.x;
    if (t < 32 && use_stoch) sidx[t] = idx[b * 32 + t];
    if (t < 10) sact[t] = act[b * 10 + t];
    __syncthreads();
    int j = t * 4;
    float4 acc = *(const float4*)(b_ih + j);
    if (use_stoch) {
        #pragma unroll 4
        for (int s = 0; s < 32; s++) {
            const float4 w = *(const float4*)(WT + (size_t)(s * 32 + sidx[s]) * 1536 + j);
            acc.x += w.x; acc.y += w.y; acc.z += w.z; acc.w += w.w;
        }
    }
    #pragma unroll
    for (int a = 0; a < 10; a++) {
        float av = sact[a];
        const float4 w = *(const float4*)(WT + (size_t)(1024 + a) * 1536 + j);
        acc.x = fmaf(av, w.x, acc.x); acc.y = fmaf(av, w.y, acc.y);
        acc.z = fmaf(av, w.z, acc.z); acc.w = fmaf(av, w.w, acc.w);
    }
    *(float4*)(gx + (size_t)b * 1536 + j) = acc;
}

// ---------------- fp32 SGEMM: C[m][n] = sum_k A[m][k]*B[n][k], K=512 ----------------
// Bitwise-identical accumulation to round-1 kernel: per output a single fp32 FMA
// chain over k ascending. BK=16, double-buffered smem, register prefetch.
// 128x128 tile, 256 threads, 8x8 micro-tile per thread.
__global__ void __launch_bounds__(256) sgemm_nt(
    const float* __restrict__ A, int lda,
    const float* __restrict__ B, int ldb,
    float* __restrict__ C, int ldc)
{
    __shared__ float As[2][16][128];
    __shared__ float Bs[2][16][128];
    const int bm = blockIdx.y * 128;
    const int bn = blockIdx.x * 128;
    const int tid = threadIdx.x;
    const int lr = tid >> 1;            // row in tile 0..127
    const int lc = (tid & 1) << 2;      // k sub-offset 0 or 4
    const float* Ap = A + (size_t)(bm + lr) * lda + lc;
    const float* Bp = B + (size_t)(bn + lr) * ldb + lc;
    const int tx = tid & 15;
    const int ty = tid >> 4;
    const int mr = ty << 3;
    const int nc = tx << 3;

    float acc[8][8];
    #pragma unroll
    for (int i = 0; i < 8; i++)
        #pragma unroll
        for (int j = 0; j < 8; j++) acc[i][j] = 0.f;

    float4 ra0, ra1, rb0, rb1;

    // prologue: slab 0 (k = lc..lc+3, lc+8..lc+11)
    ra0 = *(const float4*)(Ap);      ra1 = *(const float4*)(Ap + 8);
    rb0 = *(const float4*)(Bp);      rb1 = *(const float4*)(Bp + 8);
    {
        float a0[4], a1[4], b0[4], b1[4];
        *(float4*)a0 = ra0; *(float4*)a1 = ra1;
        *(float4*)b0 = rb0; *(float4*)b1 = rb1;
        #pragma unroll
        for (int e = 0; e < 4; e++) {
            As[0][lc + e][lr] = a0[e];     As[0][lc + 8 + e][lr] = a1[e];
            Bs[0][lc + e][lr] = b0[e];     Bs[0][lc + 8 + e][lr] = b1[e];
        }
    }
    __syncthreads();

    const int NSLAB = 512 / 16;
    for (int s = 0; s < NSLAB; s++) {
        if (s + 1 < NSLAB) {
            int k0 = (s + 1) * 16;
            ra0 = *(const float4*)(Ap + k0);      ra1 = *(const float4*)(Ap + k0 + 8);
            rb0 = *(const float4*)(Bp + k0);      rb1 = *(const float4*)(Bp + k0 + 8);
        }
        const int st = s & 1;
        #pragma unroll
        for (int k = 0; k < 16; k++) {
            float a0[8], b0[8];
            *(float4*)(a0)     = *(const float4*)&As[st][k][mr];
            *(float4*)(a0 + 4) = *(const float4*)&As[st][k][mr + 4];
            *(float4*)(b0)     = *(const float4*)&Bs[st][k][nc];
            *(float4*)(b0 + 4) = *(const float4*)&Bs[st][k][nc + 4];
            #pragma unroll
            for (int i = 0; i < 8; i++)
                #pragma unroll
                for (int j = 0; j < 8; j++)
                    acc[i][j] = fmaf(a0[i], b0[j], acc[i][j]);
        }
        if (s + 1 < NSLAB) {
            const int nst = (s + 1) & 1;
            float a0[4], a1[4], b0[4], b1[4];
            *(float4*)a0 = ra0; *(float4*)a1 = ra1;
            *(float4*)b0 = rb0; *(float4*)b1 = rb1;
            #pragma unroll
            for (int e = 0; e < 4; e++) {
                As[nst][lc + e][lr] = a0[e];     As[nst][lc + 8 + e][lr] = a1[e];
                Bs[nst][lc + e][lr] = b0[e];     Bs[nst][lc + 8 + e][lr] = b1[e];
            }
        }
        __syncthreads();
    }

    #pragma unroll
    for (int i = 0; i < 8; i++) {
        float* Crow = C + (size_t)(bm + mr + i) * ldc + bn + nc;
        *(float4*)Crow       = make_float4(acc[i][0], acc[i][1], acc[i][2], acc[i][3]);
        *(float4*)(Crow + 4) = make_float4(acc[i][4], acc[i][5], acc[i][6], acc[i][7]);
    }
}

// ---------------- GRU gate fusion ----------------
__global__ void __launch_bounds__(256) gru_gates(
    const float* __restrict__ gx, const float* __restrict__ gh,
    const float* __restrict__ b_hh,
    const float* __restrict__ hprev, int ldh,
    float* __restrict__ out_t)
{
    int i = blockIdx.x * 256 + threadIdx.x;
    int b = i >> 9, j = i & 511;
    size_t base = (size_t)b * 1536;
    float xr = gx[base + j];
    float xz = gx[base + 512 + j];
    float xn = gx[base + 1024 + j];
    float hr = gh[base + j]        + b_hh[j];
    float hz = gh[base + 512 + j]  + b_hh[512 + j];
    float hn = gh[base + 1024 + j] + b_hh[1024 + j];
    float r = sigmoid_x(xr + hr);
    float z = sigmoid_x(xz + hz);
    float n = tanhf(xn + r * hn);
    float h = hprev[(size_t)b * ldh + j];
    out_t[base + j] = (1.f - z) * n + z * h;
}

// ---------------- LayerNorm + SiLU ----------------
__global__ void __launch_bounds__(256) ln_silu(
    float* __restrict__ h1, const float* __restrict__ pb1,
    const float* __restrict__ pg, const float* __restrict__ pbeta)
{
    int gw = (blockIdx.x * 256 + threadIdx.x) >> 5;
    int lane = threadIdx.x & 31;
    float* row = h1 + (size_t)gw * 512;
    float x[16];
    float s = 0.f;
    #pragma unroll
    for (int i = 0; i < 16; i++) { x[i] = row[i * 32 + lane] + pb1[i * 32 + lane]; s += x[i]; }
    #pragma unroll
    for (int o = 16; o; o >>= 1) s += __shfl_xor_sync(0xffffffffu, s, o);
    float mu = s * (1.f / 512.f);
    float vs = 0.f;
    #pragma unroll
    for (int i = 0; i < 16; i++) { float d = x[i] - mu; vs = fmaf(d, d, vs); }
    #pragma unroll
    for (int o = 16; o; o >>= 1) vs += __shfl_xor_sync(0xffffffffu, vs, o);
    float var = vs * (1.f / 512.f) + 1e-5f;
    float rs = rsqrtf(var);
    rs = rs * (1.5f - 0.5f * var * rs * rs);
    #pragma unroll
    for (int i = 0; i < 16; i++) {
        int c = i * 32 + lane;
        float v = (x[i] - mu) * rs * pg[c] + pbeta[c];
        row[c] = v * sigmoid_x(v);
    }
}

// ---------------- categorical sampling ----------------
__global__ void __launch_bounds__(256) sample_k(
    const float* __restrict__ logits, const float* __restrict__ pb2,
    unsigned k0, unsigned k1,
    float* __restrict__ out_t, int* __restrict__ idxbuf)
{
    int w = (blockIdx.x * 256 + threadIdx.x) >> 5;
    int lane = threadIdx.x & 31;
    int b = w >> 5, s = w & 31;
    unsigned x0 = 0u, x1 = (unsigned)(b * 1024 + s * 32 + lane);
    threefry2x32(k0, k1, x0, x1);
    unsigned bits = x0 ^ x1;
    float f = __uint_as_float((bits >> 9) | 0x3f800000u) - 1.0f;
    float u = (f == 0.f) ? 1.17549435e-38f : f;
    float g = -logf(-logf(u));
    float v = logits[(size_t)b * 1024 + s * 32 + lane] + pb2[s * 32 + lane] + g;
    float bv = v; int bi = lane;
    #pragma unroll
    for (int o = 16; o; o >>= 1) {
        float ov = __shfl_xor_sync(0xffffffffu, bv, o);
        int   oi = __shfl_xor_sync(0xffffffffu, bi, o);
        if (ov > bv || (ov == bv && oi < bi)) { bv = ov; bi = oi; }
    }
    out_t[(size_t)b * 1536 + 512 + s * 32 + lane] = (lane == bi) ? 1.0f : 0.0f;
    if (lane == bi) idxbuf[b * 32 + s] = bi;
}

// ---------------- host ----------------
extern "C" void kernel_launch(void* const* d_in, const int* in_sizes, int n_in,
                              void* d_out, int out_size) {
    const float* action = (const float*)d_in[0];
    const float* deter0 = (const float*)d_in[1];
    const float* W_ih  = (const float*)d_in[3];
    const float* b_ih  = (const float*)d_in[4];
    const float* W_hh  = (const float*)d_in[5];
    const float* b_hh  = (const float*)d_in[6];
    const float* pW1   = (const float*)d_in[7];
    const float* pb1   = (const float*)d_in[8];
    const float* pg    = (const float*)d_in[9];
    const float* pbeta = (const float*)d_in[10];
    const float* pW2   = (const float*)d_in[11];
    const float* pb2   = (const float*)d_in[12];
    float* out = (float*)d_out;

    float *WT, *gx, *gh, *h1, *logits; int* idxb;
    cudaGetSymbolAddress((void**)&WT, g_WihT);
    cudaGetSymbolAddress((void**)&gx, g_gx);
    cudaGetSymbolAddress((void**)&gh, g_gh);
    cudaGetSymbolAddress((void**)&h1, g_h1);
    cudaGetSymbolAddress((void**)&logits, g_logits);
    cudaGetSymbolAddress((void**)&idxb, g_idx);

    // step keys: split(key(42), 16), partitionable mode
    unsigned kt0[16], kt1[16];
    for (int t = 0; t < 16; t++) {
        unsigned x0 = 0u, x1 = (unsigned)t;
        threefry2x32(0u, 42u, x0, x1);
        kt0[t] = x0; kt1[t] = x1;
    }

    transpose_k<<<dim3(33, 48), dim3(32, 32)>>>(W_ih, WT, 1536, 1034);

    for (int t = 0; t < 16; t++) {
        const float* act_t = action + (size_t)t * 2048 * 10;
        float* out_t = out + (size_t)t * 2048 * 1536;
        const float* hprev = t ? out + (size_t)(t - 1) * 2048 * 1536 : deter0;
        int ldh = t ? 1536 : 512;

        gather_gx<<<2048, 384>>>(WT, b_ih, idxb, act_t, gx, t > 0);
        sgemm_nt<<<dim3(12, 16), 256>>>(hprev, ldh, W_hh, 512, gh, 1536);
        gru_gates<<<4096, 256>>>(gx, gh, b_hh, hprev, ldh, out_t);
        sgemm_nt<<<dim3(4, 16), 256>>>(out_t, 1536, pW1, 512, h1, 512);
        ln_silu<<<256, 256>>>(h1, pb1, pg, pbeta);
        sgemm_nt<<<dim3(8, 16), 256>>>(h1, 512, pW2, 512, logits, 1024);
        sample_k<<<8192, 256>>>(logits, pb2, kt0[t], kt1[t], out_t, idxb);
    }
}